// round 7
// baseline (speedup 1.0000x reference)
#include <cuda_runtime.h>
#include <math.h>

#define N_EXP 8
#define CDIM  1024
#define MAX_T 8192
#define NCH   256    // rank-scan chunks (threads per block)
#define NFILL 2048   // fill blocks

// scratch (no allocation allowed -> __device__ globals)
__device__ float g_p1[MAX_T];
__device__ float g_p2[MAX_T];
__device__ int   g_e1[MAX_T];
__device__ int   g_e2[MAX_T];
__device__ unsigned int g_ticket;   // zero-initialized; reset by last block

// ---------------------------------------------------------------------------
// Single fused kernel:
//   blocks [0, ngate)          : gating GEMV + top-2 + masked softmax
//   blocks [ngate, ngate+NFILL): flat zero-fill of the whole output
//   LAST block to finish       : k-major ranks + used_capacity + scatter
// ---------------------------------------------------------------------------
__global__ void __launch_bounds__(256)
router_kernel(const float* __restrict__ x,
              const float* __restrict__ wg,
              float* __restrict__ out,
              int T, size_t out_elems, int ngate, int cap)
{
    __shared__ float wgs[N_EXP * CDIM];   // 32 KB; reused by the rank tail
    __shared__ unsigned int sTicket;

    int tid = threadIdx.x;

    if ((int)blockIdx.x >= ngate) {
        // ------------------ flat zero-fill ------------------
        size_t n4     = out_elems >> 2;
        size_t idx    = (size_t)(blockIdx.x - ngate) * blockDim.x + tid;
        size_t stride = (size_t)NFILL * blockDim.x;
        float4* o4 = (float4*)out;
        const float4 z = make_float4(0.f, 0.f, 0.f, 0.f);

        size_t i = idx;
        for (; i + 3 * stride < n4; i += 4 * stride) {
            o4[i]              = z;
            o4[i + stride]     = z;
            o4[i + 2 * stride] = z;
            o4[i + 3 * stride] = z;
        }
        for (; i < n4; i += stride) o4[i] = z;

        // scalar tail (out_elems not multiple of 4)
        if (blockIdx.x == (unsigned)ngate) {
            size_t tail = n4 << 2;
            size_t rem  = out_elems - tail;
            if (tid < (int)rem) out[tail + tid] = 0.f;
        }
    } else {
        // ------------------ gating (warp per token) ------------------
        {
            const float4* src = (const float4*)wg;
            float4*       dst = (float4*)wgs;
            for (int i = tid; i < N_EXP * CDIM / 4; i += blockDim.x)
                dst[i] = src[i];
        }
        __syncthreads();

        int warp  = tid >> 5;
        int lane  = tid & 31;
        int token = blockIdx.x * 8 + warp;

        if (token < T) {
            const float4* xr = (const float4*)(x + (size_t)token * CDIM);

            float acc[N_EXP];
#pragma unroll
            for (int e = 0; e < N_EXP; e++) acc[e] = 0.f;

#pragma unroll
            for (int it = 0; it < CDIM / 128; it++) {      // 8 iterations
                int c4 = it * 32 + lane;
                float4 xv = xr[c4];
#pragma unroll
                for (int e = 0; e < N_EXP; e++) {
                    float4 w = *(const float4*)&wgs[e * CDIM + c4 * 4];
                    acc[e] += xv.x * w.x + xv.y * w.y + xv.z * w.z + xv.w * w.w;
                }
            }
#pragma unroll
            for (int e = 0; e < N_EXP; e++) {
#pragma unroll
                for (int o = 16; o > 0; o >>= 1)
                    acc[e] += __shfl_xor_sync(0xffffffffu, acc[e], o);
            }

            if (lane == 0) {
                int e1 = 0; float l1 = acc[0];
#pragma unroll
                for (int e = 1; e < N_EXP; e++)
                    if (acc[e] > l1) { l1 = acc[e]; e1 = e; }
                int e2 = -1; float l2 = -INFINITY;
#pragma unroll
                for (int e = 0; e < N_EXP; e++)
                    if (e != e1 && acc[e] > l2) { l2 = acc[e]; e2 = e; }

                float p1 = 1.f / (1.f + expf(l2 - l1));   // stable: l2 <= l1
                float p2 = 1.f - p1;

                g_e1[token] = e1; g_e2[token] = e2;
                g_p1[token] = p1; g_p2[token] = p2;
            }
        }
        __syncthreads();   // wgs free for reuse after this (block-local)
    }

    // ---------------- last-block-done ticket ----------------
    __threadfence();                       // publish my fills / gate results
    if (tid == 0)
        sTicket = atomicAdd(&g_ticket, 1u);
    __syncthreads();
    if (sTicket != (unsigned)(gridDim.x - 1))
        return;                            // not the last block: done

    // =====================================================================
    // TAIL (one block): k-major ranks + used_capacity + scatter.
    // All other blocks' writes are visible (their fence precedes their
    // ticket increment, which precedes ours).
    // =====================================================================
    if (tid == 0) g_ticket = 0;            // reset for next graph replay

    float* out_used = out;
    float* cb       = out + N_EXP;
    float* mask     = cb + (size_t)T * N_EXP * cap;

    // reuse wgs as int scratch: s1/s2 = 2 * 256 * 9 ints = 18 KB
    int (*s1)[N_EXP + 1] = (int (*)[N_EXP + 1])wgs;
    int (*s2)[N_EXP + 1] = (int (*)[N_EXP + 1])(wgs + NCH * (N_EXP + 1));
    __shared__ int tot1[N_EXP], tot2[N_EXP];

    int per  = (T + NCH - 1) / NCH;
    int base = tid * per;
    int end  = min(base + per, T);

    __syncthreads();   // everyone past wgs float use (gate path) before int reuse

#pragma unroll
    for (int e = 0; e < N_EXP; e++) { s1[tid][e] = 0; s2[tid][e] = 0; }
    for (int t = base; t < end; t++) {
        s1[tid][g_e1[t]]++;
        s2[tid][g_e2[t]]++;
    }
    __syncthreads();

    // warp w: exclusive scan over the 256 chunk-counts of expert w
    int wid = tid >> 5, lane = tid & 31;
    if (wid < N_EXP) {
        int v1[8], v2[8];
        int sum1 = 0, sum2 = 0;
#pragma unroll
        for (int j = 0; j < 8; j++) {
            int idx = lane * 8 + j;
            v1[j] = sum1; sum1 += s1[idx][wid];
            v2[j] = sum2; sum2 += s2[idx][wid];
        }
        int inc1 = sum1, inc2 = sum2;
#pragma unroll
        for (int o = 1; o < 32; o <<= 1) {
            int a = __shfl_up_sync(0xffffffffu, inc1, o);
            int b = __shfl_up_sync(0xffffffffu, inc2, o);
            if (lane >= o) { inc1 += a; inc2 += b; }
        }
        int exc1 = inc1 - sum1, exc2 = inc2 - sum2;
#pragma unroll
        for (int j = 0; j < 8; j++) {
            int idx = lane * 8 + j;
            s1[idx][wid] = exc1 + v1[j];
            s2[idx][wid] = exc2 + v2[j];
        }
        if (lane == 31) { tot1[wid] = inc1; tot2[wid] = inc2; }
    }
    __syncthreads();

    if (tid < N_EXP)
        out_used[tid] = (float)min(tot1[tid] + tot2[tid], cap);

    // shift k=1 start offsets by total k=0 counts
#pragma unroll
    for (int e = 0; e < N_EXP; e++) s2[tid][e] += tot1[e];

    // replay chunk: assign ranks in place and scatter immediately
    for (int t = base; t < end; t++) {
        size_t row = (size_t)t * N_EXP * cap;
        int e = g_e1[t]; int r = s1[tid][e]++;
        if (r < cap) {
            float p = g_p1[t];
            size_t o = row + (size_t)e * cap + r;
            cb[o] = p;
            if (p != 0.f) mask[o] = 1.f;
        }
        e = g_e2[t]; r = s2[tid][e]++;
        if (r < cap) {
            float p = g_p2[t];
            size_t o = row + (size_t)e * cap + r;
            cb[o] = p;
            if (p != 0.f) mask[o] = 1.f;
        }
    }
}

// ---------------------------------------------------------------------------
extern "C" void kernel_launch(void* const* d_in, const int* in_sizes, int n_in,
                              void* d_out, int out_size)
{
    const float* x  = (const float*)d_in[0];
    const float* wg = (const float*)d_in[1];

    int T = in_sizes[0] / CDIM;                       // 4096
    // out layout: [used_capacity(8) | cb_weight(T*E*cap) | sec_mask(T*E*cap)]
    long long rest = (long long)out_size - N_EXP;
    int cap = (int)(rest / (2LL * T * N_EXP));        // 2048

    int ngate = (T + 7) / 8;
    router_kernel<<<ngate + NFILL, 256>>>(
        x, wg, (float*)d_out, T, (size_t)out_size, ngate, cap);
}